// round 2
// baseline (speedup 1.0000x reference)
#include <cuda_runtime.h>
#include <math.h>

#define NPIX 65536            // 256*256
#define NB 4                  // batch
#define XS96 (96L*65536)      // per-batch stride, 96-channel tensor
#define XS192 (192L*65536)    // per-batch stride, 192-channel tensor

// ---------------- scratch: ONE pooled device global (allocation-free rule) ----
// layout (floats):
//   [0,                50331648)   kvtmp  : 4*192*65536
//   [50331648,        100663296)   kvdw   : 4*192*65536
//   [100663296,       125829120)   qtmp   : 4*96*65536
//   [125829120,       150994944)   qdw    : 4*96*65536
//   [150994944,       150995712)   inv    : 768
//   [150995712,       151585280)   part   : 8*32*48*48 = 589824
//   [151585280,       151603712)   P      : 8*48*48    = 18432
//   [151603712,       151640576)   Meff   : 4*96*96    = 36864
#define OFF_KVTMP 0L
#define OFF_KVDW  50331648L
#define OFF_QTMP  100663296L
#define OFF_QDW   125829120L
#define OFF_INV   150994944L
#define OFF_PART  150995712L
#define OFF_P     151585280L
#define OFF_MEFF  151603712L
__device__ float g_pool[151640576L];

// ---------------- SGEMM: C[M,N] = W[M,96] @ X[96,65536] ----------------------
// grid: (N/128, M/96, B); block 256.  BM=96, BN=128, BK=32, TM=6, TN=8.
__global__ void __launch_bounds__(256) sgemm_k96(
    const float* __restrict__ Wp, long wStride,
    const float* __restrict__ Xp, long xStride,
    float*       __restrict__ Cp, long cStride)
{
    const int n0 = blockIdx.x * 128;
    const int m0 = blockIdx.y * 96;
    const float* W = Wp + (long)blockIdx.z * wStride;
    const float* X = Xp + (long)blockIdx.z * xStride;
    float*       C = Cp + (long)blockIdx.z * cStride;

    __shared__ float Ws[32][97];    // [k][m], padded stride
    __shared__ float Xs[32][128];   // [k][n]

    const int tid = threadIdx.x;
    const int tx = tid & 15;        // 0..15 -> 8 cols each
    const int ty = tid >> 4;        // 0..15 -> 6 rows each

    float acc[6][8];
#pragma unroll
    for (int i = 0; i < 6; i++)
#pragma unroll
        for (int j = 0; j < 8; j++) acc[i][j] = 0.f;

    for (int k0 = 0; k0 < 96; k0 += 32) {
        // W tile (96x32), stored transposed
#pragma unroll
        for (int it = 0; it < 12; it++) {
            int e = tid + it * 256;           // 0..3071
            int m = e >> 5, kk = e & 31;
            Ws[kk][m] = W[(long)(m0 + m) * 96 + k0 + kk];
        }
        // X tile (32x128), float4
#pragma unroll
        for (int it = 0; it < 4; it++) {
            int e = tid + it * 256;           // 0..1023 float4s
            int kk = e >> 5, c4 = e & 31;
            float4 v = *(const float4*)&X[(long)(k0 + kk) * NPIX + n0 + c4 * 4];
            *(float4*)&Xs[kk][c4 * 4] = v;
        }
        __syncthreads();

#pragma unroll 8
        for (int kk = 0; kk < 32; kk++) {
            float a[6];
#pragma unroll
            for (int i = 0; i < 6; i++) a[i] = Ws[kk][ty * 6 + i];
            float4 b0 = *(float4*)&Xs[kk][tx * 8];
            float4 b1 = *(float4*)&Xs[kk][tx * 8 + 4];
            float bb[8] = {b0.x, b0.y, b0.z, b0.w, b1.x, b1.y, b1.z, b1.w};
#pragma unroll
            for (int i = 0; i < 6; i++)
#pragma unroll
                for (int j = 0; j < 8; j++) acc[i][j] = fmaf(a[i], bb[j], acc[i][j]);
        }
        __syncthreads();
    }

#pragma unroll
    for (int i = 0; i < 6; i++) {
        long row = m0 + ty * 6 + i;
        float4 o0 = {acc[i][0], acc[i][1], acc[i][2], acc[i][3]};
        float4 o1 = {acc[i][4], acc[i][5], acc[i][6], acc[i][7]};
        *(float4*)&C[row * NPIX + n0 + tx * 8]     = o0;
        *(float4*)&C[row * NPIX + n0 + tx * 8 + 4] = o1;
    }
}

// ---------------- depthwise 3x3, zero pad, cross-correlation ------------------
// grid: (256 [y], C, B); block 256 (x). One block = one output row.
__global__ void __launch_bounds__(256) dwconv3_k(
    const float* __restrict__ in, const float* __restrict__ w,
    float* __restrict__ out, int C)
{
    const int x = threadIdx.x;
    const int y = blockIdx.x;
    const int c = blockIdx.y;
    const int b = blockIdx.z;
    const float* base = in + ((long)b * C + c) * NPIX;
    const float* wc = w + c * 9;

    float s = 0.f;
#pragma unroll
    for (int dy = -1; dy <= 1; dy++) {
        int yy = y + dy;
        if (yy < 0 || yy > 255) continue;
#pragma unroll
        for (int dx = -1; dx <= 1; dx++) {
            int xx = x + dx;
            if (xx < 0 || xx > 255) continue;
            s = fmaf(wc[(dy + 1) * 3 + (dx + 1)], base[yy * 256 + xx], s);
        }
    }
    out[((long)b * C + c) * NPIX + y * 256 + x] = s;
}

// ---------------- row L2-norm inverses ---------------------------------------
// grid: 768 blocks (384 q rows, 384 k rows); block 256.
__global__ void __launch_bounds__(256) norms_k(
    const float* __restrict__ qdw, const float* __restrict__ kvdw,
    float* __restrict__ inv)
{
    const int r = blockIdx.x;
    const float* p;
    if (r < 384) { int b = r / 96, c = r % 96; p = qdw  + ((long)b * 96  + c) * NPIX; }
    else { int rr = r - 384; int b = rr / 96, c = rr % 96; p = kvdw + ((long)b * 192 + c) * NPIX; }

    const float4* p4 = (const float4*)p;
    float s = 0.f;
    for (int i = threadIdx.x; i < NPIX / 4; i += 256) {
        float4 v = p4[i];
        s += v.x * v.x + v.y * v.y + v.z * v.z + v.w * v.w;
    }
#pragma unroll
    for (int o = 16; o > 0; o >>= 1) s += __shfl_down_sync(0xffffffffu, s, o);
    __shared__ float red[8];
    if ((threadIdx.x & 31) == 0) red[threadIdx.x >> 5] = s;
    __syncthreads();
    if (threadIdx.x == 0) {
        float t = 0.f;
        for (int i = 0; i < 8; i++) t += red[i];
        inv[r] = 1.f / fmaxf(sqrtf(t), 1e-12f);
    }
}

// ---------------- attn split-K partials: G = q @ k^T --------------------------
// grid: (32 chunks, 8 bh); block 256. chunk = 2048 columns.
__global__ void __launch_bounds__(256) attn_partial_k(
    const float* __restrict__ qdw, const float* __restrict__ kvdw,
    float* __restrict__ part)
{
    const int chunk = blockIdx.x;
    const int bh = blockIdx.y;
    const int b = bh >> 1, h = bh & 1;
    const float* Q = qdw  + ((long)b * 96  + h * 48) * NPIX;
    const float* K = kvdw + ((long)b * 192 + h * 48) * NPIX;
    const int n0 = chunk * 2048;

    __shared__ float Qs[32][49];
    __shared__ float Ks[32][49];

    const int tid = threadIdx.x;
    const int tx = tid & 15, ty = tid >> 4;

    float acc[3][3];
#pragma unroll
    for (int i = 0; i < 3; i++)
#pragma unroll
        for (int j = 0; j < 3; j++) acc[i][j] = 0.f;

    for (int nt = 0; nt < 64; nt++) {
        const int nb = n0 + nt * 32;
#pragma unroll
        for (int it = 0; it < 6; it++) {
            int e = tid + it * 256;           // 0..1535
            int c = e >> 5, nn = e & 31;
            Qs[nn][c] = Q[(long)c * NPIX + nb + nn];
            Ks[nn][c] = K[(long)c * NPIX + nb + nn];
        }
        __syncthreads();
#pragma unroll 8
        for (int nn = 0; nn < 32; nn++) {
            float a0 = Qs[nn][ty * 3], a1 = Qs[nn][ty * 3 + 1], a2 = Qs[nn][ty * 3 + 2];
            float b0 = Ks[nn][tx * 3], b1 = Ks[nn][tx * 3 + 1], b2 = Ks[nn][tx * 3 + 2];
            acc[0][0] = fmaf(a0, b0, acc[0][0]); acc[0][1] = fmaf(a0, b1, acc[0][1]); acc[0][2] = fmaf(a0, b2, acc[0][2]);
            acc[1][0] = fmaf(a1, b0, acc[1][0]); acc[1][1] = fmaf(a1, b1, acc[1][1]); acc[1][2] = fmaf(a1, b2, acc[1][2]);
            acc[2][0] = fmaf(a2, b0, acc[2][0]); acc[2][1] = fmaf(a2, b1, acc[2][1]); acc[2][2] = fmaf(a2, b2, acc[2][2]);
        }
        __syncthreads();
    }

    float* pout = part + ((long)bh * 32 + chunk) * 2304;
#pragma unroll
    for (int i = 0; i < 3; i++)
#pragma unroll
        for (int j = 0; j < 3; j++)
            pout[(ty * 3 + i) * 48 + tx * 3 + j] = acc[i][j];
}

// ---------------- reduce + scale + top-k softmax combine ----------------------
// grid: 8 blocks (b,h); block 256.
__global__ void __launch_bounds__(256) combine_k(
    const float* __restrict__ part, const float* __restrict__ inv,
    const float* __restrict__ temp,
    const float* __restrict__ a1, const float* __restrict__ a2,
    const float* __restrict__ a3, const float* __restrict__ a4,
    float* __restrict__ P)
{
    const int bh = blockIdx.x;
    const int b = bh >> 1, h = bh & 1;
    __shared__ float A[48][48];

    for (int e = threadIdx.x; e < 2304; e += 256) {
        float s = 0.f;
        for (int ch = 0; ch < 32; ch++) s += part[((long)bh * 32 + ch) * 2304 + e];
        int c = e / 48, d = e % 48;
        float iq = inv[b * 96 + h * 48 + c];
        float ik = inv[384 + b * 96 + h * 48 + d];
        A[c][d] = s * iq * ik * temp[h];
    }
    __syncthreads();

    if (threadIdx.x < 48) {
        const int r = threadIdx.x;
        float m = -3.4e38f;
        for (int j = 0; j < 48; j++) m = fmaxf(m, A[r][j]);
        float ev[48]; int rank[48];
        float den24 = 0.f, den32 = 0.f, den36 = 0.f, den38 = 0.f;
        for (int j = 0; j < 48; j++) {
            float vj = A[r][j];
            int cnt = 0;
            for (int i = 0; i < 48; i++) {
                float vi = A[r][i];
                cnt += (vi > vj) || (vi == vj && i < j);
            }
            rank[j] = cnt;
            float e = expf(vj - m);
            ev[j] = e;
            if (cnt < 24) den24 += e;
            if (cnt < 32) den32 += e;
            if (cnt < 36) den36 += e;
            if (cnt < 38) den38 += e;
        }
        float c1 = a1[0] / den24, c2 = a2[0] / den32, c3 = a3[0] / den36, c4 = a4[0] / den38;
        for (int j = 0; j < 48; j++) {
            float coef = (rank[j] < 24 ? c1 : 0.f) + (rank[j] < 32 ? c2 : 0.f)
                       + (rank[j] < 36 ? c3 : 0.f) + (rank[j] < 38 ? c4 : 0.f);
            P[(long)bh * 2304 + r * 48 + j] = ev[j] * coef;
        }
    }
}

// ---------------- Meff[b] = proj composed with blockdiag(P) -------------------
// grid: 4 blocks; block 256. Meff[b][o][h*48+d] = sum_c proj[o][h*48+c]*P[b,h][c][d]
__global__ void __launch_bounds__(256) meff_k(
    const float* __restrict__ P, const float* __restrict__ proj,
    float* __restrict__ M)
{
    const int b = blockIdx.x;
    for (int e = threadIdx.x; e < 96 * 96; e += 256) {
        int o = e / 96, g = e % 96;
        int h = g / 48, d = g % 48;
        float s = 0.f;
        const float* pr = proj + o * 96 + h * 48;
        const float* pp = P + ((long)(b * 2 + h)) * 2304 + d;
#pragma unroll 8
        for (int c = 0; c < 48; c++) s = fmaf(pr[c], pp[c * 48], s);
        M[b * 9216 + e] = s;
    }
}

// -----------------------------------------------------------------------------
extern "C" void kernel_launch(void* const* d_in, const int* in_sizes, int n_in,
                              void* d_out, int out_size)
{
    const float* x      = (const float*)d_in[0];
    const float* y      = (const float*)d_in[1];
    const float* temp   = (const float*)d_in[2];
    const float* kv_w   = (const float*)d_in[3];
    const float* kv_dww = (const float*)d_in[4];
    const float* q_w    = (const float*)d_in[5];
    const float* q_dww  = (const float*)d_in[6];
    const float* proj_w = (const float*)d_in[7];
    const float* a1     = (const float*)d_in[8];
    const float* a2     = (const float*)d_in[9];
    const float* a3     = (const float*)d_in[10];
    const float* a4     = (const float*)d_in[11];
    float* out = (float*)d_out;

    float* pool;
    cudaGetSymbolAddress((void**)&pool, g_pool);
    float* kvtmp = pool + OFF_KVTMP;
    float* kvdw  = pool + OFF_KVDW;
    float* qtmp  = pool + OFF_QTMP;
    float* qdw   = pool + OFF_QDW;
    float* inv   = pool + OFF_INV;
    float* part  = pool + OFF_PART;
    float* P     = pool + OFF_P;
    float* Meff  = pool + OFF_MEFF;

    // 1) kv = conv1x1(x, kv_w): [192,96]@[96,N] per batch
    sgemm_k96<<<dim3(512, 2, NB), 256>>>(kv_w, 0L, x, XS96, kvtmp, XS192);
    // 2) q = conv1x1(y, q_w)
    sgemm_k96<<<dim3(512, 1, NB), 256>>>(q_w, 0L, y, XS96, qtmp, XS96);
    // 3) depthwise 3x3
    dwconv3_k<<<dim3(256, 192, NB), 256>>>(kvtmp, kv_dww, kvdw, 192);
    dwconv3_k<<<dim3(256, 96,  NB), 256>>>(qtmp,  q_dww,  qdw,  96);
    // 4) row norms (q rows + k rows)
    norms_k<<<768, 256>>>(qdw, kvdw, inv);
    // 5) attn = q @ k^T (split-K partials)
    attn_partial_k<<<dim3(32, 8), 256>>>(qdw, kvdw, part);
    // 6) reduce + normalize + 4x top-k softmax combined into P
    combine_k<<<8, 256>>>(part, inv, temp, a1, a2, a3, a4, P);
    // 7) Meff = proj o blockdiag(P)
    meff_k<<<4, 256>>>(P, proj_w, Meff);
    // 8) out = Meff @ v  (v = kv_dw channels 96..191)
    sgemm_k96<<<dim3(512, 1, NB), 256>>>(Meff, 9216L, kvdw + 96L * NPIX, XS192, out, XS96);
}

// round 3
// speedup vs baseline: 1.0175x; 1.0175x over previous
#include <cuda_runtime.h>
#include <math.h>
#include <stdint.h>

#define NPIX 65536            // 256*256
#define NB 4                  // batch
#define XS96 (96L*65536)      // per-batch stride, 96-channel tensor
#define XS192 (192L*65536)    // per-batch stride, 192-channel tensor

// ---------------- scratch: ONE pooled device global (allocation-free rule) ----
#define OFF_KVTMP 0L
#define OFF_KVDW  50331648L                  // 4*192*65536
#define OFF_QTMP  100663296L
#define OFF_QDW   125829120L                 // 4*96*65536
#define OFF_INV   150994944L                 // 768
#define OFF_PART  150995712L                 // 8*32*48*48
#define OFF_P     151585280L                 // 8*48*48
#define OFF_MEFF  151603712L                 // 4*96*96
#define OFF_SQKV  151640576L                 // 4*192
#define OFF_SQQ   151641344L                 // 4*96
#define POOL_SZ   151641728L
__device__ float g_pool[POOL_SZ];

// ---------------- tf32 helpers -----------------------------------------------
__device__ __forceinline__ void split_tf32(float x, uint32_t& hi, uint32_t& lo) {
    uint32_t h; asm("cvt.rna.tf32.f32 %0, %1;" : "=r"(h) : "f"(x));
    float lf = x - __uint_as_float(h);
    uint32_t l; asm("cvt.rna.tf32.f32 %0, %1;" : "=r"(l) : "f"(lf));
    hi = h; lo = l;
}

__device__ __forceinline__ void mma_tf32(float c[4], const uint32_t a[4], const uint32_t b[2]) {
    asm volatile(
        "mma.sync.aligned.m16n8k8.row.col.f32.tf32.tf32.f32 "
        "{%0,%1,%2,%3}, {%4,%5,%6,%7}, {%8,%9}, {%0,%1,%2,%3};\n"
        : "+f"(c[0]), "+f"(c[1]), "+f"(c[2]), "+f"(c[3])
        : "r"(a[0]), "r"(a[1]), "r"(a[2]), "r"(a[3]), "r"(b[0]), "r"(b[1]));
}

// ---------------- split-tf32 GEMM: C[M,N] = W[M,96] @ X[96,65536] -------------
// grid: (512, M/96, B); block 256 (8 warps, 2x4). BM=96, BN=128, BK=16.
// Warp tile 48x32 = 3 mtiles x 4 ntiles of m16n8k8.
__global__ void __launch_bounds__(256) sgemm_tf32(
    const float* __restrict__ Wp, long wStride,
    const float* __restrict__ Xp, long xStride,
    float*       __restrict__ Cp, long cStride)
{
    const int n0 = blockIdx.x * 128;
    const int m0 = blockIdx.y * 96;
    const float* W = Wp + (long)blockIdx.z * wStride;
    const float* X = Xp + (long)blockIdx.z * xStride;
    float*       C = Cp + (long)blockIdx.z * cStride;

    __shared__ uint32_t WsHi[16][97], WsLo[16][97];
    __shared__ uint32_t XsHi[16][128], XsLo[16][128];

    const int tid  = threadIdx.x;
    const int wid  = tid >> 5;
    const int lane = tid & 31;
    const int gid  = lane >> 2;      // 0..7
    const int tig  = lane & 3;       // 0..3
    const int wm   = (wid >> 2) * 48;  // 0 or 48
    const int wn   = (wid & 3) * 32;   // 0,32,64,96

    float acc[3][4][4];
#pragma unroll
    for (int mt = 0; mt < 3; mt++)
#pragma unroll
        for (int nt = 0; nt < 4; nt++)
#pragma unroll
            for (int i = 0; i < 4; i++) acc[mt][nt][i] = 0.f;

    for (int k0 = 0; k0 < 96; k0 += 16) {
        // W tile (96 x 16), store [k][m] split
#pragma unroll
        for (int it = 0; it < 6; it++) {
            int e = tid + it * 256;          // 0..1535
            int m = e >> 4, kk = e & 15;
            uint32_t h, l;
            split_tf32(W[(long)(m0 + m) * 96 + k0 + kk], h, l);
            WsHi[kk][m] = h; WsLo[kk][m] = l;
        }
        // X tile (16 x 128), float4 split
#pragma unroll
        for (int it = 0; it < 2; it++) {
            int e = tid + it * 256;          // 0..511 float4s
            int kk = e >> 5, c4 = e & 31;
            float4 v = *(const float4*)&X[(long)(k0 + kk) * NPIX + n0 + c4 * 4];
            uint32_t h, l;
            split_tf32(v.x, h, l); XsHi[kk][c4*4+0] = h; XsLo[kk][c4*4+0] = l;
            split_tf32(v.y, h, l); XsHi[kk][c4*4+1] = h; XsLo[kk][c4*4+1] = l;
            split_tf32(v.z, h, l); XsHi[kk][c4*4+2] = h; XsLo[kk][c4*4+2] = l;
            split_tf32(v.w, h, l); XsHi[kk][c4*4+3] = h; XsLo[kk][c4*4+3] = l;
        }
        __syncthreads();

#pragma unroll
        for (int ks = 0; ks < 16; ks += 8) {
            const int kr0 = ks + tig, kr1 = ks + tig + 4;
            uint32_t ah[3][4], al[3][4], bh[4][2], bl[4][2];
#pragma unroll
            for (int mt = 0; mt < 3; mt++) {
                int m = wm + mt * 16 + gid;
                ah[mt][0] = WsHi[kr0][m];     al[mt][0] = WsLo[kr0][m];
                ah[mt][1] = WsHi[kr0][m + 8]; al[mt][1] = WsLo[kr0][m + 8];
                ah[mt][2] = WsHi[kr1][m];     al[mt][2] = WsLo[kr1][m];
                ah[mt][3] = WsHi[kr1][m + 8]; al[mt][3] = WsLo[kr1][m + 8];
            }
#pragma unroll
            for (int nt = 0; nt < 4; nt++) {
                int n = wn + nt * 8 + gid;
                bh[nt][0] = XsHi[kr0][n]; bl[nt][0] = XsLo[kr0][n];
                bh[nt][1] = XsHi[kr1][n]; bl[nt][1] = XsLo[kr1][n];
            }
#pragma unroll
            for (int mt = 0; mt < 3; mt++)
#pragma unroll
                for (int nt = 0; nt < 4; nt++) {
                    mma_tf32(acc[mt][nt], ah[mt], bh[nt]);
                    mma_tf32(acc[mt][nt], ah[mt], bl[nt]);
                    mma_tf32(acc[mt][nt], al[mt], bh[nt]);
                }
        }
        __syncthreads();
    }

#pragma unroll
    for (int mt = 0; mt < 3; mt++) {
        long row0 = m0 + wm + mt * 16 + gid;
#pragma unroll
        for (int nt = 0; nt < 4; nt++) {
            long col = n0 + wn + nt * 8 + 2 * tig;
            float2 u0 = {acc[mt][nt][0], acc[mt][nt][1]};
            float2 u1 = {acc[mt][nt][2], acc[mt][nt][3]};
            *(float2*)&C[row0 * NPIX + col]       = u0;
            *(float2*)&C[(row0 + 8) * NPIX + col] = u1;
        }
    }
}

// ---------------- depthwise 3x3 + fused sumsq, smem row-tiled -----------------
// grid: (16 ytiles, C, B); block 256 (one col each, 16 output rows).
__global__ void __launch_bounds__(256) dwconv3_k(
    const float* __restrict__ in, const float* __restrict__ w,
    float* __restrict__ out, int C, float* __restrict__ sq)
{
    const int tid = threadIdx.x;
    const int y0 = blockIdx.x * 16;
    const int c = blockIdx.y;
    const int b = blockIdx.z;
    const float* base = in + ((long)b * C + c) * NPIX;
    float* obase = out + ((long)b * C + c) * NPIX;

    __shared__ float S[18][258];
#pragma unroll
    for (int r = 0; r < 18; r++) {
        int gy = y0 - 1 + r;
        S[r][tid + 1] = (gy >= 0 && gy < 256) ? base[gy * 256 + tid] : 0.f;
    }
    if (tid < 18) { S[tid][0] = 0.f; S[tid][257] = 0.f; }
    __syncthreads();

    const float* wc = w + c * 9;
    const float w00 = wc[0], w01 = wc[1], w02 = wc[2];
    const float w10 = wc[3], w11 = wc[4], w12 = wc[5];
    const float w20 = wc[6], w21 = wc[7], w22 = wc[8];

    float p1 = 0.f, p2 = 0.f, lsq = 0.f;
#pragma unroll
    for (int r = 0; r < 18; r++) {
        float l = S[r][tid], m = S[r][tid + 1], rt = S[r][tid + 2];
        float t0 = fmaf(w00, l, fmaf(w01, m, w02 * rt));
        float t1 = fmaf(w10, l, fmaf(w11, m, w12 * rt));
        float t2 = fmaf(w20, l, fmaf(w21, m, w22 * rt));
        if (r >= 2) {
            float o = p2 + t2;
            obase[(y0 + r - 2) * 256 + tid] = o;
            lsq = fmaf(o, o, lsq);
        }
        p2 = p1 + t1;
        p1 = t0;
    }

    // block-reduce sumsq -> one atomic per block
#pragma unroll
    for (int o = 16; o > 0; o >>= 1) lsq += __shfl_down_sync(0xffffffffu, lsq, o);
    __shared__ float red[8];
    if ((tid & 31) == 0) red[tid >> 5] = lsq;
    __syncthreads();
    if (tid == 0) {
        float s = 0.f;
        for (int i = 0; i < 8; i++) s += red[i];
        atomicAdd(&sq[b * C + c], s);
    }
}

// ---------------- sumsq -> inverse norms --------------------------------------
__global__ void inv_k(const float* __restrict__ sq_q, const float* __restrict__ sq_kv,
                      float* __restrict__ inv)
{
    int r = blockIdx.x * 256 + threadIdx.x;
    if (r >= 768) return;
    float s;
    if (r < 384) s = sq_q[r];
    else { int rr = r - 384; s = sq_kv[(rr / 96) * 192 + (rr % 96)]; }
    inv[r] = 1.f / fmaxf(sqrtf(s), 1e-12f);
}

// ---------------- attn split-K partials: G = q @ k^T --------------------------
// grid: (32 chunks, 8 bh); block 256. chunk = 2048 columns.
__global__ void __launch_bounds__(256) attn_partial_k(
    const float* __restrict__ qdw, const float* __restrict__ kvdw,
    float* __restrict__ part)
{
    const int chunk = blockIdx.x;
    const int bh = blockIdx.y;
    const int b = bh >> 1, h = bh & 1;
    const float* Q = qdw  + ((long)b * 96  + h * 48) * NPIX;
    const float* K = kvdw + ((long)b * 192 + h * 48) * NPIX;
    const int n0 = chunk * 2048;

    __shared__ float Qs[32][49];
    __shared__ float Ks[32][49];

    const int tid = threadIdx.x;
    const int tx = tid & 15, ty = tid >> 4;

    float acc[3][3];
#pragma unroll
    for (int i = 0; i < 3; i++)
#pragma unroll
        for (int j = 0; j < 3; j++) acc[i][j] = 0.f;

    for (int nt = 0; nt < 64; nt++) {
        const int nb = n0 + nt * 32;
#pragma unroll
        for (int it = 0; it < 6; it++) {
            int e = tid + it * 256;           // 0..1535
            int c = e >> 5, nn = e & 31;
            Qs[nn][c] = Q[(long)c * NPIX + nb + nn];
            Ks[nn][c] = K[(long)c * NPIX + nb + nn];
        }
        __syncthreads();
#pragma unroll 8
        for (int nn = 0; nn < 32; nn++) {
            float a0 = Qs[nn][ty * 3], a1 = Qs[nn][ty * 3 + 1], a2 = Qs[nn][ty * 3 + 2];
            float b0 = Ks[nn][tx * 3], b1 = Ks[nn][tx * 3 + 1], b2 = Ks[nn][tx * 3 + 2];
            acc[0][0] = fmaf(a0, b0, acc[0][0]); acc[0][1] = fmaf(a0, b1, acc[0][1]); acc[0][2] = fmaf(a0, b2, acc[0][2]);
            acc[1][0] = fmaf(a1, b0, acc[1][0]); acc[1][1] = fmaf(a1, b1, acc[1][1]); acc[1][2] = fmaf(a1, b2, acc[1][2]);
            acc[2][0] = fmaf(a2, b0, acc[2][0]); acc[2][1] = fmaf(a2, b1, acc[2][1]); acc[2][2] = fmaf(a2, b2, acc[2][2]);
        }
        __syncthreads();
    }

    float* pout = part + ((long)bh * 32 + chunk) * 2304;
#pragma unroll
    for (int i = 0; i < 3; i++)
#pragma unroll
        for (int j = 0; j < 3; j++)
            pout[(ty * 3 + i) * 48 + tx * 3 + j] = acc[i][j];
}

// ---------------- reduce + scale + top-k softmax combine ----------------------
__global__ void __launch_bounds__(256) combine_k(
    const float* __restrict__ part, const float* __restrict__ inv,
    const float* __restrict__ temp,
    const float* __restrict__ a1, const float* __restrict__ a2,
    const float* __restrict__ a3, const float* __restrict__ a4,
    float* __restrict__ P)
{
    const int bh = blockIdx.x;
    const int b = bh >> 1, h = bh & 1;
    __shared__ float A[48][48];

    for (int e = threadIdx.x; e < 2304; e += 256) {
        float s = 0.f;
        for (int ch = 0; ch < 32; ch++) s += part[((long)bh * 32 + ch) * 2304 + e];
        int c = e / 48, d = e % 48;
        float iq = inv[b * 96 + h * 48 + c];
        float ik = inv[384 + b * 96 + h * 48 + d];
        A[c][d] = s * iq * ik * temp[h];
    }
    __syncthreads();

    if (threadIdx.x < 48) {
        const int r = threadIdx.x;
        float m = -3.4e38f;
        for (int j = 0; j < 48; j++) m = fmaxf(m, A[r][j]);
        float ev[48]; int rank[48];
        float den24 = 0.f, den32 = 0.f, den36 = 0.f, den38 = 0.f;
        for (int j = 0; j < 48; j++) {
            float vj = A[r][j];
            int cnt = 0;
            for (int i = 0; i < 48; i++) {
                float vi = A[r][i];
                cnt += (vi > vj) || (vi == vj && i < j);
            }
            rank[j] = cnt;
            float e = expf(vj - m);
            ev[j] = e;
            if (cnt < 24) den24 += e;
            if (cnt < 32) den32 += e;
            if (cnt < 36) den36 += e;
            if (cnt < 38) den38 += e;
        }
        float c1 = a1[0] / den24, c2 = a2[0] / den32, c3 = a3[0] / den36, c4 = a4[0] / den38;
        for (int j = 0; j < 48; j++) {
            float coef = (rank[j] < 24 ? c1 : 0.f) + (rank[j] < 32 ? c2 : 0.f)
                       + (rank[j] < 36 ? c3 : 0.f) + (rank[j] < 38 ? c4 : 0.f);
            P[(long)bh * 2304 + r * 48 + j] = ev[j] * coef;
        }
    }
}

// ---------------- Meff[b] = proj composed with blockdiag(P) -------------------
__global__ void __launch_bounds__(256) meff_k(
    const float* __restrict__ P, const float* __restrict__ proj,
    float* __restrict__ M)
{
    const int b = blockIdx.x;
    for (int e = threadIdx.x; e < 96 * 96; e += 256) {
        int o = e / 96, g = e % 96;
        int h = g / 48, d = g % 48;
        float s = 0.f;
        const float* pr = proj + o * 96 + h * 48;
        const float* pp = P + ((long)(b * 2 + h)) * 2304 + d;
#pragma unroll 8
        for (int c = 0; c < 48; c++) s = fmaf(pr[c], pp[c * 48], s);
        M[b * 9216 + e] = s;
    }
}

// -----------------------------------------------------------------------------
extern "C" void kernel_launch(void* const* d_in, const int* in_sizes, int n_in,
                              void* d_out, int out_size)
{
    const float* x      = (const float*)d_in[0];
    const float* y      = (const float*)d_in[1];
    const float* temp   = (const float*)d_in[2];
    const float* kv_w   = (const float*)d_in[3];
    const float* kv_dww = (const float*)d_in[4];
    const float* q_w    = (const float*)d_in[5];
    const float* q_dww  = (const float*)d_in[6];
    const float* proj_w = (const float*)d_in[7];
    const float* a1     = (const float*)d_in[8];
    const float* a2     = (const float*)d_in[9];
    const float* a3     = (const float*)d_in[10];
    const float* a4     = (const float*)d_in[11];
    float* out = (float*)d_out;

    float* pool;
    cudaGetSymbolAddress((void**)&pool, g_pool);
    float* kvtmp = pool + OFF_KVTMP;
    float* kvdw  = pool + OFF_KVDW;
    float* qtmp  = pool + OFF_QTMP;
    float* qdw   = pool + OFF_QDW;
    float* inv   = pool + OFF_INV;
    float* part  = pool + OFF_PART;
    float* P     = pool + OFF_P;
    float* Meff  = pool + OFF_MEFF;
    float* sq_kv = pool + OFF_SQKV;
    float* sq_q  = pool + OFF_SQQ;

    // 0) zero fused-norm accumulators (graph-capturable memset node)
    cudaMemsetAsync(sq_kv, 0, (768 + 384) * sizeof(float));
    // 1) kv = conv1x1(x, kv_w): [192,96]@[96,N] per batch (split-tf32 MMA)
    sgemm_tf32<<<dim3(512, 2, NB), 256>>>(kv_w, 0L, x, XS96, kvtmp, XS192);
    // 2) q = conv1x1(y, q_w)
    sgemm_tf32<<<dim3(512, 1, NB), 256>>>(q_w, 0L, y, XS96, qtmp, XS96);
    // 3) depthwise 3x3 (+ fused sumsq)
    dwconv3_k<<<dim3(16, 192, NB), 256>>>(kvtmp, kv_dww, kvdw, 192, sq_kv);
    dwconv3_k<<<dim3(16, 96,  NB), 256>>>(qtmp,  q_dww,  qdw,  96,  sq_q);
    // 4) inverse norms
    inv_k<<<3, 256>>>(sq_q, sq_kv, inv);
    // 5) attn = q @ k^T (split-K partials, fp32 exact)
    attn_partial_k<<<dim3(32, 8), 256>>>(qdw, kvdw, part);
    // 6) reduce + normalize + 4x top-k softmax combined into P
    combine_k<<<8, 256>>>(part, inv, temp, a1, a2, a3, a4, P);
    // 7) Meff = proj o blockdiag(P)
    meff_k<<<4, 256>>>(P, proj_w, Meff);
    // 8) out = Meff @ v  (v = kvdw channels 96..191)
    sgemm_tf32<<<dim3(512, 1, NB), 256>>>(Meff, 9216L, kvdw + 96L * NPIX, XS192, out, XS96);
}

// round 6
// speedup vs baseline: 1.8279x; 1.7964x over previous
#include <cuda_runtime.h>
#include <cuda_bf16.h>
#include <math.h>
#include <stdint.h>

#define NPIX 65536L           // 256*256
#define NB 4                  // batch
#define XS96 (96L*65536)      // per-batch stride, 96-ch fp32 tensor
#define XS192 (192L*65536)

// ---------------- pooled scratch (floats) -------------------------------------
// vhi/vlo ALIAS xhi/xlo: x planes are dead after GEMM-1; dwconv writes v planes
// after GEMM-2; GEMM-3 reads them last. Sequential stream => disjoint lifetimes.
#define OFF_KVTMP 0L                      // 4*192*65536  fp32 conv1x1(x)
#define OFF_QTMP  50331648L               // 4*96*65536   fp32 conv1x1(y)
#define OFF_KDW   75497472L               // 4*96*65536   fp32 k half post-dw
#define OFF_QDW   100663296L              // 4*96*65536   fp32 q post-dw
#define OFF_XHI   125829120L              // bf16 plane (12582912 floats) -- reused as VHI
#define OFF_XLO   138412032L              //                               -- reused as VLO
#define OFF_YHI   150994944L
#define OFF_YLO   163577856L
#define OFF_INV   176160768L              // 768
#define OFF_PART  176161536L              // 8*32*48*48
#define OFF_P     176751360L              // 8*48*48
#define OFF_MHI   176769792L              // bf16 4*96*96 -> 18432 floats
#define OFF_MLO   176788224L
#define OFF_WHI   176806656L              // bf16 27648 -> 13824 floats
#define OFF_WLO   176820480L
#define OFF_SQKV  176834304L              // 384
#define OFF_SQQ   176834688L              // 384
#define POOL_SZ   176835072L
__device__ __align__(256) float g_pool[POOL_SZ];

// ---------------- helpers -----------------------------------------------------
__device__ __forceinline__ void bf_split(float x, __nv_bfloat16& h, __nv_bfloat16& l) {
    h = __float2bfloat16_rn(x);
    l = __float2bfloat16_rn(x - __bfloat162float(h));
}
__device__ __forceinline__ uint32_t pck(const __nv_bfloat16* a, const __nv_bfloat16* b) {
    uint32_t x = *(const uint16_t*)a, y = *(const uint16_t*)b;
    return x | (y << 16);
}
__device__ __forceinline__ void mma_bf16(float c[4], const uint32_t a[4], const uint32_t b[2]) {
    asm volatile(
        "mma.sync.aligned.m16n8k16.row.col.f32.bf16.bf16.f32 "
        "{%0,%1,%2,%3}, {%4,%5,%6,%7}, {%8,%9}, {%0,%1,%2,%3};\n"
        : "+f"(c[0]), "+f"(c[1]), "+f"(c[2]), "+f"(c[3])
        : "r"(a[0]), "r"(a[1]), "r"(a[2]), "r"(a[3]), "r"(b[0]), "r"(b[1]));
}
__device__ __forceinline__ void cpa16(void* dst, const void* src) {
    unsigned d = (unsigned)__cvta_generic_to_shared(dst);
    asm volatile("cp.async.ca.shared.global [%0], [%1], 16;\n" :: "r"(d), "l"(src));
}

// ---------------- elementwise fp32 -> bf16 hi/lo planes -----------------------
__global__ void __launch_bounds__(256) split_k(
    const float4* __restrict__ in, uint2* __restrict__ hi, uint2* __restrict__ lo, long n4)
{
    long i = (long)blockIdx.x * 256 + threadIdx.x;
    if (i >= n4) return;
    float4 v = in[i];
    __nv_bfloat16 hx, lx, hy, ly, hz, lz, hw, lw;
    bf_split(v.x, hx, lx); bf_split(v.y, hy, ly);
    bf_split(v.z, hz, lz); bf_split(v.w, hw, lw);
    uint2 H, L;
    H.x = pck(&hx, &hy); H.y = pck(&hz, &hw);
    L.x = pck(&lx, &ly); L.y = pck(&lz, &lw);
    hi[i] = H; lo[i] = L;
}

// ---------------- weights -> bf16 planes (kv_w then q_w concatenated) ---------
__global__ void wsplit_k(const float* __restrict__ kv_w, const float* __restrict__ q_w,
                         __nv_bfloat16* __restrict__ hi, __nv_bfloat16* __restrict__ lo)
{
    int i = blockIdx.x * 256 + threadIdx.x;
    if (i >= 27648) return;
    float v = (i < 18432) ? kv_w[i] : q_w[i - 18432];
    bf_split(v, hi[i], lo[i]);
}

// ---------------- 3-term bf16 GEMM: C[M,N] = W[M,96] @ X[96,65536] ------------
// grid (512, M/96, NB); block 256 (8 warps 2x4); BM=96 BN=128 BK=16, 2-stage.
__global__ void __launch_bounds__(256) gemm_bf3(
    const __nv_bfloat16* __restrict__ WhiP, const __nv_bfloat16* __restrict__ WloP, long wStride,
    const __nv_bfloat16* __restrict__ XhiP, const __nv_bfloat16* __restrict__ XloP, long xStride,
    float* __restrict__ Cp, long cStride)
{
    const int n0 = blockIdx.x * 128;
    const int m0 = blockIdx.y * 96;
    const __nv_bfloat16* Whi = WhiP + (long)blockIdx.z * wStride;
    const __nv_bfloat16* Wlo = WloP + (long)blockIdx.z * wStride;
    const __nv_bfloat16* Xhi = XhiP + (long)blockIdx.z * xStride;
    const __nv_bfloat16* Xlo = XloP + (long)blockIdx.z * xStride;
    float* C = Cp + (long)blockIdx.z * cStride;

    // cp.async.16 REQUIRES 16B-aligned smem destinations -> force alignment.
    __shared__ __align__(16) __nv_bfloat16 sWh[2][96][16];
    __shared__ __align__(16) __nv_bfloat16 sWl[2][96][16];
    __shared__ __align__(16) __nv_bfloat16 sXh[2][16][136];   // 272B rows (16B-mult), padded
    __shared__ __align__(16) __nv_bfloat16 sXl[2][16][136];

    const int tid  = threadIdx.x;
    const int wid  = tid >> 5;
    const int lane = tid & 31;
    const int gid  = lane >> 2;
    const int tig  = lane & 3;
    const int wm   = (wid >> 2) * 48;
    const int wn   = (wid & 3) * 32;

    float acc[3][4][4];
#pragma unroll
    for (int mt = 0; mt < 3; mt++)
#pragma unroll
        for (int nt = 0; nt < 4; nt++)
#pragma unroll
            for (int i = 0; i < 4; i++) acc[mt][nt][i] = 0.f;

#define LOAD_STAGE(buf, k0) do { \
    if (tid < 192) { \
        int m = tid >> 1, half = tid & 1; \
        long g = (long)(m0 + m) * 96 + (k0) + half * 8; \
        cpa16(&sWh[buf][m][half * 8], Whi + g); \
        cpa16(&sWl[buf][m][half * 8], Wlo + g); \
    } \
    { \
        int kk = tid >> 4, seg = tid & 15; \
        long g = (long)((k0) + kk) * NPIX + n0 + seg * 8; \
        cpa16(&sXh[buf][kk][seg * 8], Xhi + g); \
        cpa16(&sXl[buf][kk][seg * 8], Xlo + g); \
    } \
    asm volatile("cp.async.commit_group;\n"); \
} while (0)

    LOAD_STAGE(0, 0);
    LOAD_STAGE(1, 16);
    asm volatile("cp.async.wait_group 1;\n");
    __syncthreads();

#pragma unroll 1
    for (int s = 0; s < 6; s++) {
        const int buf = s & 1;
        uint32_t ah[3][4], al[3][4], bh[4][2], bl[4][2];
#pragma unroll
        for (int mt = 0; mt < 3; mt++) {
            int m = wm + mt * 16 + gid;
            ah[mt][0] = *(const uint32_t*)&sWh[buf][m][2 * tig];
            ah[mt][1] = *(const uint32_t*)&sWh[buf][m + 8][2 * tig];
            ah[mt][2] = *(const uint32_t*)&sWh[buf][m][2 * tig + 8];
            ah[mt][3] = *(const uint32_t*)&sWh[buf][m + 8][2 * tig + 8];
            al[mt][0] = *(const uint32_t*)&sWl[buf][m][2 * tig];
            al[mt][1] = *(const uint32_t*)&sWl[buf][m + 8][2 * tig];
            al[mt][2] = *(const uint32_t*)&sWl[buf][m][2 * tig + 8];
            al[mt][3] = *(const uint32_t*)&sWl[buf][m + 8][2 * tig + 8];
        }
#pragma unroll
        for (int nt = 0; nt < 4; nt++) {
            int n = wn + nt * 8 + gid;
            bh[nt][0] = pck(&sXh[buf][2 * tig][n],     &sXh[buf][2 * tig + 1][n]);
            bh[nt][1] = pck(&sXh[buf][2 * tig + 8][n], &sXh[buf][2 * tig + 9][n]);
            bl[nt][0] = pck(&sXl[buf][2 * tig][n],     &sXl[buf][2 * tig + 1][n]);
            bl[nt][1] = pck(&sXl[buf][2 * tig + 8][n], &sXl[buf][2 * tig + 9][n]);
        }
#pragma unroll
        for (int mt = 0; mt < 3; mt++)
#pragma unroll
            for (int nt = 0; nt < 4; nt++) {
                mma_bf16(acc[mt][nt], ah[mt], bh[nt]);
                mma_bf16(acc[mt][nt], ah[mt], bl[nt]);
                mma_bf16(acc[mt][nt], al[mt], bh[nt]);
            }
        __syncthreads();
        if (s + 2 < 6) LOAD_STAGE(buf, (s + 2) * 16);
        if (s < 5) {
            if (s + 2 < 6) asm volatile("cp.async.wait_group 1;\n");
            else           asm volatile("cp.async.wait_group 0;\n");
            __syncthreads();
        }
    }
#undef LOAD_STAGE

#pragma unroll
    for (int mt = 0; mt < 3; mt++) {
        long row0 = m0 + wm + mt * 16 + gid;
#pragma unroll
        for (int nt = 0; nt < 4; nt++) {
            long col = n0 + wn + nt * 8 + 2 * tig;
            float2 u0 = {acc[mt][nt][0], acc[mt][nt][1]};
            float2 u1 = {acc[mt][nt][2], acc[mt][nt][3]};
            *(float2*)&C[row0 * NPIX + col]       = u0;
            *(float2*)&C[(row0 + 8) * NPIX + col] = u1;
        }
    }
}

// ---------------- depthwise 3x3 + fused sumsq / bf16 v-planes -----------------
// grid: (16 ytiles, inC, B); block 256.
__global__ void __launch_bounds__(256) dwconv3_k(
    const float* __restrict__ in, const float* __restrict__ w,
    float* __restrict__ outf, int inC, float* __restrict__ sq,
    __nv_bfloat16* __restrict__ vhi, __nv_bfloat16* __restrict__ vlo)
{
    const int tid = threadIdx.x;
    const int y0 = blockIdx.x * 16;
    const int c = blockIdx.y;
    const int b = blockIdx.z;
    const float* base = in + ((long)b * inC + c) * NPIX;
    const bool isv = (vhi != nullptr) && (c >= 96);

    __shared__ float S[18][258];
#pragma unroll
    for (int r = 0; r < 18; r++) {
        int gy = y0 - 1 + r;
        S[r][tid + 1] = (gy >= 0 && gy < 256) ? base[gy * 256 + tid] : 0.f;
    }
    if (tid < 18) { S[tid][0] = 0.f; S[tid][257] = 0.f; }
    __syncthreads();

    const float* wc = w + c * 9;
    const float w00 = wc[0], w01 = wc[1], w02 = wc[2];
    const float w10 = wc[3], w11 = wc[4], w12 = wc[5];
    const float w20 = wc[6], w21 = wc[7], w22 = wc[8];

    float* ob = outf + ((long)b * 96 + c) * NPIX;
    __nv_bfloat16* vh = isv ? vhi + ((long)b * 96 + (c - 96)) * NPIX : nullptr;
    __nv_bfloat16* vl = isv ? vlo + ((long)b * 96 + (c - 96)) * NPIX : nullptr;

    float p1 = 0.f, p2 = 0.f, lsq = 0.f;
#pragma unroll
    for (int r = 0; r < 18; r++) {
        float l = S[r][tid], m = S[r][tid + 1], rt = S[r][tid + 2];
        float t0 = fmaf(w00, l, fmaf(w01, m, w02 * rt));
        float t1 = fmaf(w10, l, fmaf(w11, m, w12 * rt));
        float t2 = fmaf(w20, l, fmaf(w21, m, w22 * rt));
        if (r >= 2) {
            float o = p2 + t2;
            long idx = (long)(y0 + r - 2) * 256 + tid;
            if (isv) {
                __nv_bfloat16 h, lw2; bf_split(o, h, lw2);
                vh[idx] = h; vl[idx] = lw2;
            } else {
                ob[idx] = o;
                lsq = fmaf(o, o, lsq);
            }
        }
        p2 = p1 + t1;
        p1 = t0;
    }

    if (!isv) {
#pragma unroll
        for (int o = 16; o > 0; o >>= 1) lsq += __shfl_down_sync(0xffffffffu, lsq, o);
        __shared__ float red[8];
        if ((tid & 31) == 0) red[tid >> 5] = lsq;
        __syncthreads();
        if (tid == 0) {
            float s = 0.f;
            for (int i = 0; i < 8; i++) s += red[i];
            atomicAdd(&sq[b * 96 + c], s);
        }
    }
}

// ---------------- sumsq -> inverse norms --------------------------------------
__global__ void inv_k(const float* __restrict__ sq_q, const float* __restrict__ sq_kv,
                      float* __restrict__ inv)
{
    int r = blockIdx.x * 256 + threadIdx.x;
    if (r >= 768) return;
    float s = (r < 384) ? sq_q[r] : sq_kv[r - 384];
    inv[r] = 1.f / fmaxf(sqrtf(s), 1e-12f);
}

// ---------------- attn split-K partials: G = q @ k^T (fp32 exact) -------------
__global__ void __launch_bounds__(256) attn_partial_k(
    const float* __restrict__ qdw, const float* __restrict__ kdw,
    float* __restrict__ part)
{
    const int chunk = blockIdx.x;
    const int bh = blockIdx.y;
    const int b = bh >> 1, h = bh & 1;
    const float* Q = qdw + ((long)b * 96 + h * 48) * NPIX;
    const float* K = kdw + ((long)b * 96 + h * 48) * NPIX;
    const int n0 = chunk * 2048;

    __shared__ float Qs[32][49];
    __shared__ float Ks[32][49];

    const int tid = threadIdx.x;
    const int tx = tid & 15, ty = tid >> 4;

    float acc[3][3];
#pragma unroll
    for (int i = 0; i < 3; i++)
#pragma unroll
        for (int j = 0; j < 3; j++) acc[i][j] = 0.f;

    for (int nt = 0; nt < 64; nt++) {
        const int nb = n0 + nt * 32;
#pragma unroll
        for (int it = 0; it < 6; it++) {
            int e = tid + it * 256;
            int c = e >> 5, nn = e & 31;
            Qs[nn][c] = Q[(long)c * NPIX + nb + nn];
            Ks[nn][c] = K[(long)c * NPIX + nb + nn];
        }
        __syncthreads();
#pragma unroll 8
        for (int nn = 0; nn < 32; nn++) {
            float a0 = Qs[nn][ty * 3], a1 = Qs[nn][ty * 3 + 1], a2 = Qs[nn][ty * 3 + 2];
            float b0 = Ks[nn][tx * 3], b1 = Ks[nn][tx * 3 + 1], b2 = Ks[nn][tx * 3 + 2];
            acc[0][0] = fmaf(a0, b0, acc[0][0]); acc[0][1] = fmaf(a0, b1, acc[0][1]); acc[0][2] = fmaf(a0, b2, acc[0][2]);
            acc[1][0] = fmaf(a1, b0, acc[1][0]); acc[1][1] = fmaf(a1, b1, acc[1][1]); acc[1][2] = fmaf(a1, b2, acc[1][2]);
            acc[2][0] = fmaf(a2, b0, acc[2][0]); acc[2][1] = fmaf(a2, b1, acc[2][1]); acc[2][2] = fmaf(a2, b2, acc[2][2]);
        }
        __syncthreads();
    }

    float* pout = part + ((long)bh * 32 + chunk) * 2304;
#pragma unroll
    for (int i = 0; i < 3; i++)
#pragma unroll
        for (int j = 0; j < 3; j++)
            pout[(ty * 3 + i) * 48 + tx * 3 + j] = acc[i][j];
}

// ---------------- reduce + scale + top-k softmax combine ----------------------
__global__ void __launch_bounds__(256) combine_k(
    const float* __restrict__ part, const float* __restrict__ inv,
    const float* __restrict__ temp,
    const float* __restrict__ a1, const float* __restrict__ a2,
    const float* __restrict__ a3, const float* __restrict__ a4,
    float* __restrict__ P)
{
    const int bh = blockIdx.x;
    const int b = bh >> 1, h = bh & 1;
    __shared__ float A[48][48];

    for (int e = threadIdx.x; e < 2304; e += 256) {
        float s = 0.f;
        for (int ch = 0; ch < 32; ch++) s += part[((long)bh * 32 + ch) * 2304 + e];
        int c = e / 48, d = e % 48;
        float iq = inv[b * 96 + h * 48 + c];
        float ik = inv[384 + b * 96 + h * 48 + d];
        A[c][d] = s * iq * ik * temp[h];
    }
    __syncthreads();

    if (threadIdx.x < 48) {
        const int r = threadIdx.x;
        float m = -3.4e38f;
        for (int j = 0; j < 48; j++) m = fmaxf(m, A[r][j]);
        float ev[48]; int rank[48];
        float den24 = 0.f, den32 = 0.f, den36 = 0.f, den38 = 0.f;
        for (int j = 0; j < 48; j++) {
            float vj = A[r][j];
            int cnt = 0;
            for (int i = 0; i < 48; i++) {
                float vi = A[r][i];
                cnt += (vi > vj) || (vi == vj && i < j);
            }
            rank[j] = cnt;
            float e = expf(vj - m);
            ev[j] = e;
            if (cnt < 24) den24 += e;
            if (cnt < 32) den32 += e;
            if (cnt < 36) den36 += e;
            if (cnt < 38) den38 += e;
        }
        float c1 = a1[0] / den24, c2 = a2[0] / den32, c3 = a3[0] / den36, c4 = a4[0] / den38;
        for (int j = 0; j < 48; j++) {
            float coef = (rank[j] < 24 ? c1 : 0.f) + (rank[j] < 32 ? c2 : 0.f)
                       + (rank[j] < 36 ? c3 : 0.f) + (rank[j] < 38 ? c4 : 0.f);
            P[(long)bh * 2304 + r * 48 + j] = ev[j] * coef;
        }
    }
}

// ---------------- Meff = proj o blockdiag(P), emitted as bf16 planes ----------
__global__ void __launch_bounds__(256) meff_k(
    const float* __restrict__ P, const float* __restrict__ proj,
    __nv_bfloat16* __restrict__ Mhi, __nv_bfloat16* __restrict__ Mlo)
{
    const int b = blockIdx.x;
    for (int e = threadIdx.x; e < 96 * 96; e += 256) {
        int o = e / 96, g = e % 96;
        int h = g / 48, d = g % 48;
        float s = 0.f;
        const float* pr = proj + o * 96 + h * 48;
        const float* pp = P + ((long)(b * 2 + h)) * 2304 + d;
#pragma unroll 8
        for (int c = 0; c < 48; c++) s = fmaf(pr[c], pp[c * 48], s);
        bf_split(s, Mhi[b * 9216 + e], Mlo[b * 9216 + e]);
    }
}

// -----------------------------------------------------------------------------
extern "C" void kernel_launch(void* const* d_in, const int* in_sizes, int n_in,
                              void* d_out, int out_size)
{
    const float* x      = (const float*)d_in[0];
    const float* y      = (const float*)d_in[1];
    const float* temp   = (const float*)d_in[2];
    const float* kv_w   = (const float*)d_in[3];
    const float* kv_dww = (const float*)d_in[4];
    const float* q_w    = (const float*)d_in[5];
    const float* q_dww  = (const float*)d_in[6];
    const float* proj_w = (const float*)d_in[7];
    const float* a1     = (const float*)d_in[8];
    const float* a2     = (const float*)d_in[9];
    const float* a3     = (const float*)d_in[10];
    const float* a4     = (const float*)d_in[11];
    float* out = (float*)d_out;

    float* pool;
    cudaGetSymbolAddress((void**)&pool, g_pool);
    float* kvtmp = pool + OFF_KVTMP;
    float* qtmp  = pool + OFF_QTMP;
    float* kdw   = pool + OFF_KDW;
    float* qdw   = pool + OFF_QDW;
    float* inv   = pool + OFF_INV;
    float* part  = pool + OFF_PART;
    float* P     = pool + OFF_P;
    float* sq_kv = pool + OFF_SQKV;
    float* sq_q  = pool + OFF_SQQ;
    __nv_bfloat16* xhi = (__nv_bfloat16*)(pool + OFF_XHI);
    __nv_bfloat16* xlo = (__nv_bfloat16*)(pool + OFF_XLO);
    __nv_bfloat16* yhi = (__nv_bfloat16*)(pool + OFF_YHI);
    __nv_bfloat16* ylo = (__nv_bfloat16*)(pool + OFF_YLO);
    __nv_bfloat16* vhi = xhi;   // alias: x planes dead after GEMM-1
    __nv_bfloat16* vlo = xlo;
    __nv_bfloat16* Mhi = (__nv_bfloat16*)(pool + OFF_MHI);
    __nv_bfloat16* Mlo = (__nv_bfloat16*)(pool + OFF_MLO);
    __nv_bfloat16* whi = (__nv_bfloat16*)(pool + OFF_WHI);
    __nv_bfloat16* wlo = (__nv_bfloat16*)(pool + OFF_WLO);

    const long n4 = 4L * 96 * NPIX / 4;   // 6291456 float4s per 96-ch tensor

    // 0) zero fused-norm accumulators
    cudaMemsetAsync(sq_kv, 0, 768 * sizeof(float));
    // 0b) split inputs + weights into bf16 hi/lo planes
    split_k<<<24576, 256>>>((const float4*)x, (uint2*)xhi, (uint2*)xlo, n4);
    split_k<<<24576, 256>>>((const float4*)y, (uint2*)yhi, (uint2*)ylo, n4);
    wsplit_k<<<108, 256>>>(kv_w, q_w, whi, wlo);
    // 1) kv = conv1x1(x, kv_w): [192,96]@[96,N] per batch
    gemm_bf3<<<dim3(512, 2, NB), 256>>>(whi, wlo, 0L, xhi, xlo, XS96, kvtmp, XS192);
    // 2) q = conv1x1(y, q_w)  (weights at offset 18432 in plane)
    gemm_bf3<<<dim3(512, 1, NB), 256>>>(whi + 18432, wlo + 18432, 0L, yhi, ylo, XS96, qtmp, XS96);
    // 3) depthwise 3x3: kv -> k fp32 (+sumsq) & v bf16 planes; q -> fp32 (+sumsq)
    dwconv3_k<<<dim3(16, 192, NB), 256>>>(kvtmp, kv_dww, kdw, 192, sq_kv, vhi, vlo);
    dwconv3_k<<<dim3(16, 96,  NB), 256>>>(qtmp,  q_dww,  qdw,  96,  sq_q, nullptr, nullptr);
    // 4) inverse norms
    inv_k<<<3, 256>>>(sq_q, sq_kv, inv);
    // 5) attn = q @ k^T (split-K partials, fp32 exact)
    attn_partial_k<<<dim3(32, 8), 256>>>(qdw, kdw, part);
    // 6) reduce + normalize + 4x top-k softmax combined into P
    combine_k<<<8, 256>>>(part, inv, temp, a1, a2, a3, a4, P);
    // 7) Meff = proj o blockdiag(P) -> bf16 planes
    meff_k<<<4, 256>>>(P, proj_w, Mhi, Mlo);
    // 8) out = Meff @ v
    gemm_bf3<<<dim3(512, 1, NB), 256>>>(Mhi, Mlo, 9216L, vhi, vlo, XS96, out, XS96);
}